// round 12
// baseline (speedup 1.0000x reference)
#include <cuda_runtime.h>
#include <cstdint>

// Fixed shapes: B=8, H=W=64, C=256, red=64, G=16, GC=16, kk=9, E=144, NPIX=32768
#define NPIX 32768

// wgt scratch in [g][pix][9] layout: 16*32768*9 floats = 18.9MB
__device__ float g_wgt[(size_t)16 * NPIX * 9];

typedef unsigned long long ull;

__device__ __forceinline__ ull pack2(float lo, float hi) {
    ull r; asm("mov.b64 %0, {%1, %2};" : "=l"(r) : "f"(lo), "f"(hi)); return r;
}
__device__ __forceinline__ void unpack2(ull v, float& lo, float& hi) {
    asm("mov.b64 {%0, %1}, %2;" : "=f"(lo), "=f"(hi) : "l"(v));
}
__device__ __forceinline__ void ffma2(ull& d, ull a, ull b) {
    asm("fma.rn.f32x2 %0, %1, %2, %0;" : "+l"(d) : "l"(a), "l"(b));
}
// pack two f32 into bf16x2: LOW half = f_even (lower k index), HIGH half = f_odd
__device__ __forceinline__ unsigned bfpack(float f_even, float f_odd) {
    unsigned r; asm("cvt.rn.bf16x2.f32 %0, %1, %2;" : "=r"(r) : "f"(f_odd), "f"(f_even)); return r;
}
__device__ __forceinline__ float bflo(unsigned u) { return __uint_as_float(u << 16); }
__device__ __forceinline__ float bfhi(unsigned u) { return __uint_as_float(u & 0xffff0000u); }

__device__ __forceinline__ void mma_bf16(float* c, const unsigned* a, unsigned b0, unsigned b1) {
    asm("mma.sync.aligned.m16n8k16.row.col.f32.bf16.bf16.f32 "
        "{%0,%1,%2,%3}, {%4,%5,%6,%7}, {%8,%9}, {%0,%1,%2,%3};"
        : "+f"(c[0]), "+f"(c[1]), "+f"(c[2]), "+f"(c[3])
        : "r"(a[0]), "r"(a[1]), "r"(a[2]), "r"(a[3]), "r"(b0), "r"(b1));
}

// =====================================================================
// K1: unchanged from R11 (passed, ~47.6us).
// =====================================================================
#define K1_SM_WORDS 23040

__global__ void __launch_bounds__(512, 2) wgt_kernel(
    const float* __restrict__ x,
    const float* __restrict__ W1, const float* __restrict__ b1,
    const float* __restrict__ W2, const float* __restrict__ b2)
{
    extern __shared__ float sm[];
    unsigned* xhi  = (unsigned*)sm;            // [64][68]
    unsigned* xlo  = xhi + 4352;               // [64][68]
    unsigned* w1hi = xlo + 4352;               // [64][72]
    unsigned* w1lo = w1hi + 4608;              // [64][72]
    float*    ts    = sm;                      // overlay [64][68]
    float*    W2tmp = sm + 4352;               // overlay [64][148]
    float*    W2t   = sm + 13824;              // overlay [144][64]

    const int tid  = threadIdx.x;
    const int pix0 = blockIdx.x * 64;

    const int w = tid >> 5, lane = tid & 31;
    const int quad = lane >> 2, tq = lane & 3;
    const int mw = w & 3, nw = w >> 2;

    float cfr[2][4];
    #pragma unroll
    for (int nt = 0; nt < 2; nt++)
        #pragma unroll
        for (int j = 0; j < 4; j++) cfr[nt][j] = 0.f;

    for (int chunk = 0; chunk < 2; chunk++) {
        for (int j = tid; j < 2048; j += 512) {
            int r = j >> 5, c4 = j & 31;
            float4 v = *(const float4*)(x + (size_t)(pix0 + r) * 256 + chunk * 128 + c4 * 4);
            unsigned h0 = bfpack(v.x, v.y);
            unsigned l0 = bfpack(v.x - bflo(h0), v.y - bfhi(h0));
            unsigned h1 = bfpack(v.z, v.w);
            unsigned l1 = bfpack(v.z - bflo(h1), v.w - bfhi(h1));
            int base = r * 68 + 2 * c4;
            xhi[base] = h0; xhi[base + 1] = h1;
            xlo[base] = l0; xlo[base + 1] = l1;
        }
        for (int j = tid; j < 4096; j += 512) {
            int kpl = j >> 6, c = j & 63;
            int krow = chunk * 128 + 2 * kpl;
            float f0 = W1[(size_t)krow * 64 + c];
            float f1 = W1[(size_t)(krow + 1) * 64 + c];
            unsigned h = bfpack(f0, f1);
            unsigned l = bfpack(f0 - bflo(h), f1 - bfhi(h));
            w1hi[kpl * 72 + c] = h;
            w1lo[kpl * 72 + c] = l;
        }
        __syncthreads();

        {
            const int r0 = mw * 16 + quad;
            const unsigned* xh0 = &xhi[r0 * 68];
            const unsigned* xh8 = &xhi[(r0 + 8) * 68];
            const unsigned* xl0 = &xlo[r0 * 68];
            const unsigned* xl8 = &xlo[(r0 + 8) * 68];
            #pragma unroll
            for (int ks = 0; ks < 8; ks++) {
                const int kp = 8 * ks + tq;
                unsigned ah[4], al[4];
                ah[0] = xh0[kp];     ah[1] = xh8[kp];
                ah[2] = xh0[kp + 4]; ah[3] = xh8[kp + 4];
                al[0] = xl0[kp];     al[1] = xl8[kp];
                al[2] = xl0[kp + 4]; al[3] = xl8[kp + 4];
                #pragma unroll
                for (int nt = 0; nt < 2; nt++) {
                    const int n0 = nw * 16 + nt * 8 + quad;
                    unsigned b0h = w1hi[kp * 72 + n0];
                    unsigned b1h = w1hi[(kp + 4) * 72 + n0];
                    unsigned b0l = w1lo[kp * 72 + n0];
                    unsigned b1l = w1lo[(kp + 4) * 72 + n0];
                    mma_bf16(cfr[nt], ah, b0h, b1h);
                    mma_bf16(cfr[nt], ah, b0l, b1l);
                    mma_bf16(cfr[nt], al, b0h, b1h);
                }
            }
        }
        __syncthreads();
    }

    {
        const int r0 = mw * 16 + quad;
        #pragma unroll
        for (int nt = 0; nt < 2; nt++) {
            const int nb = nw * 16 + nt * 8 + 2 * tq;
            float bia0 = b1[nb], bia1 = b1[nb + 1];
            ts[r0 * 68 + nb]           = cfr[nt][0] + bia0;
            ts[r0 * 68 + nb + 1]       = cfr[nt][1] + bia1;
            ts[(r0 + 8) * 68 + nb]     = cfr[nt][2] + bia0;
            ts[(r0 + 8) * 68 + nb + 1] = cfr[nt][3] + bia1;
        }
    }
    {
        const float4* src = (const float4*)W2;
        for (int i = tid; i < 2304; i += 512) {
            int r = i / 36, c4 = i - r * 36;
            *(float4*)&W2tmp[r * 148 + c4 * 4] = src[i];
        }
    }
    __syncthreads();

    for (int i = tid; i < 9216; i += 512) {
        int e = i >> 6, k = i & 63;
        W2t[e * 64 + k] = W2tmp[k * 148 + e];
    }
    __syncthreads();

    const int g = w;
    ull  acc[2][4];
    float acc8[2];
    {
        const float* bb = b2 + g * 9;
        ull b01 = pack2(bb[0], bb[1]), b23 = pack2(bb[2], bb[3]);
        ull b45 = pack2(bb[4], bb[5]), b67 = pack2(bb[6], bb[7]);
        float b8 = bb[8];
        #pragma unroll
        for (int pi = 0; pi < 2; pi++) {
            acc[pi][0] = b01; acc[pi][1] = b23; acc[pi][2] = b45; acc[pi][3] = b67;
            acc8[pi] = b8;
        }
    }
    {
        const float* t0r = &ts[lane * 68];
        const float* t1r = &ts[(lane + 32) * 68];
        const float* wb  = &W2t[g * 9 * 64];
        for (int k = 0; k < 64; k += 4) {
            float4 t0 = *(const float4*)&t0r[k];
            float4 t1 = *(const float4*)&t1r[k];
            {
                float4 w8 = *(const float4*)&wb[8 * 64 + k];
                #pragma unroll
                for (int kk = 0; kk < 4; kk++) {
                    acc8[0] = fmaf((&t0.x)[kk], (&w8.x)[kk], acc8[0]);
                    acc8[1] = fmaf((&t1.x)[kk], (&w8.x)[kk], acc8[1]);
                }
            }
            #pragma unroll
            for (int jp = 0; jp < 4; jp++) {
                float4 wa = *(const float4*)&wb[(2 * jp) * 64 + k];
                float4 wc = *(const float4*)&wb[(2 * jp + 1) * 64 + k];
                #pragma unroll
                for (int kk = 0; kk < 4; kk++) {
                    ull W = pack2((&wa.x)[kk], (&wc.x)[kk]);
                    float a0 = (&t0.x)[kk];
                    float a1 = (&t1.x)[kk];
                    ffma2(acc[0][jp], pack2(a0, a0), W);
                    ffma2(acc[1][jp], pack2(a1, a1), W);
                }
            }
        }
    }
    #pragma unroll
    for (int pi = 0; pi < 2; pi++) {
        const int px = lane + 32 * pi;
        float wr[9];
        unpack2(acc[pi][0], wr[0], wr[1]); unpack2(acc[pi][1], wr[2], wr[3]);
        unpack2(acc[pi][2], wr[4], wr[5]); unpack2(acc[pi][3], wr[6], wr[7]);
        wr[8] = acc8[pi];
        float* dst = g_wgt + ((size_t)g * NPIX + pix0 + px) * 9;
        #pragma unroll
        for (int j = 0; j < 9; j++) dst[j] = wr[j];
    }
}

// =====================================================================
// K2: involution — persistent, double-buffered cp.async pipeline.
// grid = 152 (1 CTA/SM), 512 threads, smem = 2 x 104 KB halo buffers.
// Each CTA owns tiles t = bid, bid+152, ... (3-4 tiles). While computing
// tile t it prefetches tile t+152 (cp.async, zero-fill OOB).
// =====================================================================
#define XS 260
#define TILE_WORDS (100 * XS)            // 26000
#define K2_SM_FLOATS (2 * TILE_WORDS)    // 52000 -> 208000 B
#define NBLK2 152
#define NTILE 512

__device__ __forceinline__ void prefetch_tile(float* dst, const float* __restrict__ x,
                                              int t, int tid) {
    const int b  = t >> 6;
    const int h0 = ((t >> 3) & 7) * 8;
    const int w0 = (t & 7) * 8;
    for (int i = tid; i < 6400; i += 512) {
        int slot = i >> 6, c4 = i & 63;
        int py = slot / 10, px = slot - py * 10;
        int gh = h0 + py - 1, gw = w0 + px - 1;
        bool ok = ((unsigned)gh < 64u) && ((unsigned)gw < 64u);
        const float* src = x + ((size_t)((b * 64 + (ok ? gh : 0)) * 64 + (ok ? gw : 0))) * 256 + c4 * 4;
        unsigned saddr = (unsigned)__cvta_generic_to_shared(dst + slot * XS + c4 * 4);
        int n = ok ? 16 : 0;
        asm volatile("cp.async.cg.shared.global [%0], [%1], 16, %2;"
                     :: "r"(saddr), "l"(src), "r"(n));
    }
}

__global__ void __launch_bounds__(512, 1) invo_kernel(
    const float* __restrict__ x, float* __restrict__ out)
{
    extern __shared__ float sm[];
    const int tid  = threadIdx.x;
    const int lane = tid & 31, g = tid >> 5;
    const int py0 = lane >> 3, pxx = lane & 7;

    // prologue: prefetch first tile
    prefetch_tile(sm, x, blockIdx.x, tid);
    asm volatile("cp.async.commit_group;");

    int buf = 0;
    for (int t = blockIdx.x; t < NTILE; t += NBLK2) {
        const int tn = t + NBLK2;
        if (tn < NTILE) prefetch_tile(sm + (buf ^ 1) * TILE_WORDS, x, tn, tid);
        asm volatile("cp.async.commit_group;");

        const int b  = t >> 6;
        const int h0 = ((t >> 3) & 7) * 8;
        const int w0 = (t & 7) * 8;

        // wgt loads overlap with the cp.async wait
        float wr[2][9];
        #pragma unroll
        for (int pi = 0; pi < 2; pi++) {
            const int py = py0 + 4 * pi;
            const int gpix = (b * 64 + h0 + py) * 64 + w0 + pxx;
            const float* src = g_wgt + ((size_t)g * NPIX + gpix) * 9;
            #pragma unroll
            for (int j = 0; j < 9; j++) wr[pi][j] = src[j];
        }

        asm volatile("cp.async.wait_group 1;");
        __syncthreads();

        const float* xs = sm + buf * TILE_WORDS;
        const int base0 = (py0 * 10 + pxx) * XS;      // window top-left slot
        float* orow0 = out + ((size_t)((b * 64 + h0 + py0) * 64 + w0 + pxx)) * 256 + g * 16;
        float* orow1 = orow0 + (size_t)4 * 64 * 256;

        #pragma unroll
        for (int gcc = 0; gcc < 4; gcc++) {
            float o0[4] = {0.f, 0.f, 0.f, 0.f};
            float o1[4] = {0.f, 0.f, 0.f, 0.f};
            #pragma unroll
            for (int u = 0; u < 9; u++) {
                int f  = g * 144 + gcc * 36 + 4 * u;
                int n  = f >> 8;              // neighbor, constant across the float4
                int ch = f & 255;
                int ni = n / 3, nj = n - ni * 3;
                int off = (ni * 10 + nj) * XS + ch;
                float4 v0 = *(const float4*)&xs[base0 + off];
                float4 v1 = *(const float4*)&xs[base0 + 40 * XS + off];
                const int i0 = 4 * u;
                o0[(i0 + 0) / 9] = fmaf(wr[0][(i0 + 0) % 9], v0.x, o0[(i0 + 0) / 9]);
                o0[(i0 + 1) / 9] = fmaf(wr[0][(i0 + 1) % 9], v0.y, o0[(i0 + 1) / 9]);
                o0[(i0 + 2) / 9] = fmaf(wr[0][(i0 + 2) % 9], v0.z, o0[(i0 + 2) / 9]);
                o0[(i0 + 3) / 9] = fmaf(wr[0][(i0 + 3) % 9], v0.w, o0[(i0 + 3) / 9]);
                o1[(i0 + 0) / 9] = fmaf(wr[1][(i0 + 0) % 9], v1.x, o1[(i0 + 0) / 9]);
                o1[(i0 + 1) / 9] = fmaf(wr[1][(i0 + 1) % 9], v1.y, o1[(i0 + 1) / 9]);
                o1[(i0 + 2) / 9] = fmaf(wr[1][(i0 + 2) % 9], v1.z, o1[(i0 + 2) / 9]);
                o1[(i0 + 3) / 9] = fmaf(wr[1][(i0 + 3) % 9], v1.w, o1[(i0 + 3) / 9]);
            }
            *(float4*)&orow0[gcc * 4] = make_float4(o0[0], o0[1], o0[2], o0[3]);
            *(float4*)&orow1[gcc * 4] = make_float4(o1[0], o1[1], o1[2], o1[3]);
        }
        __syncthreads();     // buffer consumed; next iter may overwrite it
        buf ^= 1;
    }
}

extern "C" void kernel_launch(void* const* d_in, const int* in_sizes, int n_in,
                              void* d_out, int out_size) {
    const float* x  = (const float*)d_in[0];
    const float* W1 = (const float*)d_in[1];
    const float* b1 = (const float*)d_in[2];
    const float* W2 = (const float*)d_in[3];
    const float* b2 = (const float*)d_in[4];
    float* out = (float*)d_out;

    const int SM1 = K1_SM_WORDS * 4;    // 92160 B
    const int SM2 = K2_SM_FLOATS * 4;   // 208000 B
    cudaFuncSetAttribute(wgt_kernel,  cudaFuncAttributeMaxDynamicSharedMemorySize, SM1);
    cudaFuncSetAttribute(invo_kernel, cudaFuncAttributeMaxDynamicSharedMemorySize, SM2);

    wgt_kernel<<<512, 512, SM1>>>(x, W1, b1, W2, b2);
    invo_kernel<<<NBLK2, 512, SM2>>>(x, out);
}

// round 14
// speedup vs baseline: 1.2682x; 1.2682x over previous
#include <cuda_runtime.h>
#include <cstdint>

// Fixed shapes: B=8, H=W=64, C=256, red=64, G=16, GC=16, kk=9, E=144, NPIX=32768
#define XS 260
#define NBLK 152
#define NTILE 512

typedef unsigned long long ull;

__device__ __forceinline__ ull pack2(float lo, float hi) {
    ull r; asm("mov.b64 %0, {%1, %2};" : "=l"(r) : "f"(lo), "f"(hi)); return r;
}
__device__ __forceinline__ void unpack2(ull v, float& lo, float& hi) {
    asm("mov.b64 {%0, %1}, %2;" : "=f"(lo), "=f"(hi) : "l"(v));
}
__device__ __forceinline__ void ffma2(ull& d, ull a, ull b) {
    asm("fma.rn.f32x2 %0, %1, %2, %0;" : "+l"(d) : "l"(a), "l"(b));
}
// pack two f32 into bf16x2: LOW half = f_even, HIGH half = f_odd
__device__ __forceinline__ unsigned bfpack(float f_even, float f_odd) {
    unsigned r; asm("cvt.rn.bf16x2.f32 %0, %1, %2;" : "=r"(r) : "f"(f_odd), "f"(f_even)); return r;
}
__device__ __forceinline__ float bflo(unsigned u) { return __uint_as_float(u << 16); }
__device__ __forceinline__ float bfhi(unsigned u) { return __uint_as_float(u & 0xffff0000u); }

__device__ __forceinline__ void mma_bf16(float* c, const unsigned* a, unsigned b0, unsigned b1) {
    asm("mma.sync.aligned.m16n8k16.row.col.f32.bf16.bf16.f32 "
        "{%0,%1,%2,%3}, {%4,%5,%6,%7}, {%8,%9}, {%0,%1,%2,%3};"
        : "+f"(c[0]), "+f"(c[1]), "+f"(c[2]), "+f"(c[3])
        : "r"(a[0]), "r"(a[1]), "r"(a[2]), "r"(a[3]), "r"(b0), "r"(b1));
}

// smem word layout (total 53136 words = 212544 B):
//   [0..26000)       halo  [100][260]
//   [26000..30352)   xhi   [64][68]      | overlay after stage A: ts[64][68]
//   [30352..34704)   xlo   [64][68]
//   [34704..39312)   w1hi  [64][72]
//   [39312..43920)   w1lo  [64][72]
//   [43920..53136)   W2t   [144][64]  (persistent; stride 64 keeps float4 alignment,
//                                      stage-B reads are warp-uniform broadcasts)
#define OFF_XHI  26000
#define OFF_XLO  30352
#define OFF_W1HI 34704
#define OFF_W1LO 39312
#define OFF_W2T  43920
#define SM_WORDS 53136

__device__ __forceinline__ void prefetch_halo(float* dst, const float* __restrict__ x,
                                              int t, int tid) {
    const int b  = t >> 6;
    const int h0 = ((t >> 3) & 7) * 8;
    const int w0 = (t & 7) * 8;
    for (int i = tid; i < 6400; i += 512) {
        int slot = i >> 6, c4 = i & 63;
        int py = slot / 10, px = slot - py * 10;
        int gh = h0 + py - 1, gw = w0 + px - 1;
        bool ok = ((unsigned)gh < 64u) && ((unsigned)gw < 64u);
        const float* src = x + ((size_t)((b * 64 + (ok ? gh : 0)) * 64 + (ok ? gw : 0))) * 256 + c4 * 4;
        unsigned saddr = (unsigned)__cvta_generic_to_shared(dst + slot * XS + c4 * 4);
        int n = ok ? 16 : 0;
        asm volatile("cp.async.cg.shared.global [%0], [%1], 16, %2;"
                     :: "r"(saddr), "l"(src), "r"(n));
    }
}

__global__ void __launch_bounds__(512, 1) invo_fused(
    const float* __restrict__ x,
    const float* __restrict__ W1, const float* __restrict__ b1,
    const float* __restrict__ W2, const float* __restrict__ b2,
    float* __restrict__ out)
{
    extern __shared__ float sm[];
    float*    halo = sm;
    unsigned* xhi  = (unsigned*)(sm + OFF_XHI);
    unsigned* xlo  = (unsigned*)(sm + OFF_XLO);
    unsigned* w1hi = (unsigned*)(sm + OFF_W1HI);
    unsigned* w1lo = (unsigned*)(sm + OFF_W1LO);
    float*    W2t  = sm + OFF_W2T;           // [144][64]
    float*    ts   = sm + OFF_XHI;           // overlay [64][68]

    const int tid  = threadIdx.x;
    const int w    = tid >> 5, lane = tid & 31;
    const int quad = lane >> 2, tq = lane & 3;
    const int mw   = w & 3,  nw = w >> 2;
    const int g    = w;                       // group per warp (stage B + invo)
    const int py0  = lane >> 3, pxx = lane & 7;

    // ---- prologue: prefetch first halo; build W2t (overlaps the async load) ----
    prefetch_halo(halo, x, blockIdx.x, tid);
    asm volatile("cp.async.commit_group;");
    for (int i = tid; i < 9216; i += 512) {      // coalesced gmem read, transpose store
        int k = i / 144, e = i - k * 144;
        W2t[e * 64 + k] = W2[i];
    }

    for (int t = blockIdx.x; t < NTILE; t += NBLK) {
        const int b  = t >> 6;
        const int h0 = ((t >> 3) & 7) * 8;
        const int w0 = (t & 7) * 8;

        float cfr[2][4];
        #pragma unroll
        for (int nt = 0; nt < 2; nt++)
            #pragma unroll
            for (int j = 0; j < 4; j++) cfr[nt][j] = 0.f;

        // W1 chunk0 conversion overlaps the halo cp.async wait
        for (int j = tid; j < 4096; j += 512) {
            int kpl = j >> 6, c = j & 63;
            float f0 = W1[(size_t)(2 * kpl) * 64 + c];
            float f1 = W1[(size_t)(2 * kpl + 1) * 64 + c];
            unsigned h = bfpack(f0, f1);
            unsigned l = bfpack(f0 - bflo(h), f1 - bfhi(h));
            w1hi[kpl * 72 + c] = h;
            w1lo[kpl * 72 + c] = l;
        }
        asm volatile("cp.async.wait_group 0;");
        __syncthreads();          // halo ready; W2t ready (tile0); prev tile fully done

        // ---- Stage A over 2 K-chunks of 128 channels ----
        for (int chunk = 0; chunk < 2; chunk++) {
            if (chunk == 1) {     // W1 chunk1 (chunk0 done above)
                for (int j = tid; j < 4096; j += 512) {
                    int kpl = j >> 6, c = j & 63;
                    int krow = 128 + 2 * kpl;
                    float f0 = W1[(size_t)krow * 64 + c];
                    float f1 = W1[(size_t)(krow + 1) * 64 + c];
                    unsigned h = bfpack(f0, f1);
                    unsigned l = bfpack(f0 - bflo(h), f1 - bfhi(h));
                    w1hi[kpl * 72 + c] = h;
                    w1lo[kpl * 72 + c] = l;
                }
            }
            // x chunk: read center pixels from halo smem, convert to hi/lo pairs
            for (int j = tid; j < 2048; j += 512) {
                int r = j >> 5, c4 = j & 31;
                int slot = ((r >> 3) + 1) * 10 + (r & 7) + 1;
                float4 v = *(const float4*)&halo[slot * XS + chunk * 128 + c4 * 4];
                unsigned h0v = bfpack(v.x, v.y);
                unsigned l0v = bfpack(v.x - bflo(h0v), v.y - bfhi(h0v));
                unsigned h1v = bfpack(v.z, v.w);
                unsigned l1v = bfpack(v.z - bflo(h1v), v.w - bfhi(h1v));
                int base = r * 68 + 2 * c4;
                xhi[base] = h0v; xhi[base + 1] = h1v;
                xlo[base] = l0v; xlo[base + 1] = l1v;
            }
            __syncthreads();

            {   // mma: 16 warps = 4m x 4n; warp = m16 x 2 n8-tiles; 8 k16-steps
                const int r0 = mw * 16 + quad;
                const unsigned* xh0 = &xhi[r0 * 68];
                const unsigned* xh8 = &xhi[(r0 + 8) * 68];
                const unsigned* xl0 = &xlo[r0 * 68];
                const unsigned* xl8 = &xlo[(r0 + 8) * 68];
                #pragma unroll
                for (int ks = 0; ks < 8; ks++) {
                    const int kp = 8 * ks + tq;
                    unsigned ah[4], al[4];
                    ah[0] = xh0[kp];     ah[1] = xh8[kp];
                    ah[2] = xh0[kp + 4]; ah[3] = xh8[kp + 4];
                    al[0] = xl0[kp];     al[1] = xl8[kp];
                    al[2] = xl0[kp + 4]; al[3] = xl8[kp + 4];
                    #pragma unroll
                    for (int nt = 0; nt < 2; nt++) {
                        const int n0 = nw * 16 + nt * 8 + quad;
                        unsigned b0h = w1hi[kp * 72 + n0];
                        unsigned b1h = w1hi[(kp + 4) * 72 + n0];
                        unsigned b0l = w1lo[kp * 72 + n0];
                        unsigned b1l = w1lo[(kp + 4) * 72 + n0];
                        mma_bf16(cfr[nt], ah, b0h, b1h);
                        mma_bf16(cfr[nt], ah, b0l, b1l);
                        mma_bf16(cfr[nt], al, b0h, b1h);
                    }
                }
            }
            __syncthreads();      // buffers reusable
        }

        // ---- write ts (+b1) into xhi overlay ----
        {
            const int r0 = mw * 16 + quad;
            #pragma unroll
            for (int nt = 0; nt < 2; nt++) {
                const int nb = nw * 16 + nt * 8 + 2 * tq;
                float bia0 = b1[nb], bia1 = b1[nb + 1];
                ts[r0 * 68 + nb]           = cfr[nt][0] + bia0;
                ts[r0 * 68 + nb + 1]       = cfr[nt][1] + bia1;
                ts[(r0 + 8) * 68 + nb]     = cfr[nt][2] + bia0;
                ts[(r0 + 8) * 68 + nb + 1] = cfr[nt][3] + bia1;
            }
        }
        __syncthreads();

        // ---- Stage B: FFMA2, warp-uniform g; wgt stays in registers ----
        ull  acc[2][4];
        float acc8[2];
        {
            const float* bb = b2 + g * 9;
            ull b01 = pack2(bb[0], bb[1]), b23 = pack2(bb[2], bb[3]);
            ull b45 = pack2(bb[4], bb[5]), b67 = pack2(bb[6], bb[7]);
            float b8 = bb[8];
            #pragma unroll
            for (int pi = 0; pi < 2; pi++) {
                acc[pi][0] = b01; acc[pi][1] = b23; acc[pi][2] = b45; acc[pi][3] = b67;
                acc8[pi] = b8;
            }
        }
        {
            const float* t0r = &ts[lane * 68];
            const float* t1r = &ts[(lane + 32) * 68];
            const float* wb  = &W2t[(g * 9) * 64];
            for (int k = 0; k < 64; k += 4) {
                float4 t0 = *(const float4*)&t0r[k];
                float4 t1 = *(const float4*)&t1r[k];
                {
                    float4 w8 = *(const float4*)&wb[8 * 64 + k];   // uniform
                    #pragma unroll
                    for (int kk = 0; kk < 4; kk++) {
                        acc8[0] = fmaf((&t0.x)[kk], (&w8.x)[kk], acc8[0]);
                        acc8[1] = fmaf((&t1.x)[kk], (&w8.x)[kk], acc8[1]);
                    }
                }
                #pragma unroll
                for (int jp = 0; jp < 4; jp++) {
                    float4 wa = *(const float4*)&wb[(2 * jp) * 64 + k];       // uniform
                    float4 wc = *(const float4*)&wb[(2 * jp + 1) * 64 + k];   // uniform
                    #pragma unroll
                    for (int kk = 0; kk < 4; kk++) {
                        ull W = pack2((&wa.x)[kk], (&wc.x)[kk]);
                        float a0 = (&t0.x)[kk];
                        float a1 = (&t1.x)[kk];
                        ffma2(acc[0][jp], pack2(a0, a0), W);
                        ffma2(acc[1][jp], pack2(a1, a1), W);
                    }
                }
            }
        }
        float wr[2][9];
        #pragma unroll
        for (int pi = 0; pi < 2; pi++) {
            unpack2(acc[pi][0], wr[pi][0], wr[pi][1]);
            unpack2(acc[pi][1], wr[pi][2], wr[pi][3]);
            unpack2(acc[pi][2], wr[pi][4], wr[pi][5]);
            unpack2(acc[pi][3], wr[pi][6], wr[pi][7]);
            wr[pi][8] = acc8[pi];
        }

        // ---- involution (reads halo + wr regs) ----
        const int base0 = (py0 * 10 + pxx) * XS;
        float* orow0 = out + ((size_t)((b * 64 + h0 + py0) * 64 + w0 + pxx)) * 256 + g * 16;
        float* orow1 = orow0 + (size_t)4 * 64 * 256;

        #pragma unroll
        for (int gcc = 0; gcc < 4; gcc++) {
            float o0[4] = {0.f, 0.f, 0.f, 0.f};
            float o1[4] = {0.f, 0.f, 0.f, 0.f};
            #pragma unroll
            for (int u = 0; u < 9; u++) {
                int f  = g * 144 + gcc * 36 + 4 * u;
                int n  = f >> 8;
                int ch = f & 255;
                int ni = n / 3, nj = n - ni * 3;
                int off = (ni * 10 + nj) * XS + ch;
                float4 v0 = *(const float4*)&halo[base0 + off];
                float4 v1 = *(const float4*)&halo[base0 + 40 * XS + off];
                const int i0 = 4 * u;
                o0[(i0 + 0) / 9] = fmaf(wr[0][(i0 + 0) % 9], v0.x, o0[(i0 + 0) / 9]);
                o0[(i0 + 1) / 9] = fmaf(wr[0][(i0 + 1) % 9], v0.y, o0[(i0 + 1) / 9]);
                o0[(i0 + 2) / 9] = fmaf(wr[0][(i0 + 2) % 9], v0.z, o0[(i0 + 2) / 9]);
                o0[(i0 + 3) / 9] = fmaf(wr[0][(i0 + 3) % 9], v0.w, o0[(i0 + 3) / 9]);
                o1[(i0 + 0) / 9] = fmaf(wr[1][(i0 + 0) % 9], v1.x, o1[(i0 + 0) / 9]);
                o1[(i0 + 1) / 9] = fmaf(wr[1][(i0 + 1) % 9], v1.y, o1[(i0 + 1) / 9]);
                o1[(i0 + 2) / 9] = fmaf(wr[1][(i0 + 2) % 9], v1.z, o1[(i0 + 2) / 9]);
                o1[(i0 + 3) / 9] = fmaf(wr[1][(i0 + 3) % 9], v1.w, o1[(i0 + 3) / 9]);
            }
            *(float4*)&orow0[gcc * 4] = make_float4(o0[0], o0[1], o0[2], o0[3]);
            *(float4*)&orow1[gcc * 4] = make_float4(o1[0], o1[1], o1[2], o1[3]);
        }
        __syncthreads();          // halo consumed; safe to prefetch next tile

        if (t + NBLK < NTILE) {
            prefetch_halo(halo, x, t + NBLK, tid);
            asm volatile("cp.async.commit_group;");
        }
    }
}

extern "C" void kernel_launch(void* const* d_in, const int* in_sizes, int n_in,
                              void* d_out, int out_size) {
    const float* x  = (const float*)d_in[0];
    const float* W1 = (const float*)d_in[1];
    const float* b1 = (const float*)d_in[2];
    const float* W2 = (const float*)d_in[3];
    const float* b2 = (const float*)d_in[4];
    float* out = (float*)d_out;

    const int SM = SM_WORDS * 4;   // 212544 B
    cudaFuncSetAttribute(invo_fused, cudaFuncAttributeMaxDynamicSharedMemorySize, SM);
    invo_fused<<<NBLK, 512, SM>>>(x, W1, b1, W2, b2, out);
}

// round 15
// speedup vs baseline: 1.3460x; 1.0613x over previous
#include <cuda_runtime.h>
#include <cstdint>

// Fixed shapes: B=8, H=W=64, C=256, red=64, G=16, GC=16, kk=9, E=144
// Tiling: 4x8 pixel tiles -> 1024 tiles, persistent grid of 152.
#define NBLK 152
#define NTILE 1024

typedef unsigned long long ull;

__device__ __forceinline__ ull pack2(float lo, float hi) {
    ull r; asm("mov.b64 %0, {%1, %2};" : "=l"(r) : "f"(lo), "f"(hi)); return r;
}
__device__ __forceinline__ void unpack2(ull v, float& lo, float& hi) {
    asm("mov.b64 {%0, %1}, %2;" : "=f"(lo), "=f"(hi) : "l"(v));
}
__device__ __forceinline__ void ffma2(ull& d, ull a, ull b) {
    asm("fma.rn.f32x2 %0, %1, %2, %0;" : "+l"(d) : "l"(a), "l"(b));
}
// pack two f32 into bf16x2: LOW half = f_even, HIGH half = f_odd
__device__ __forceinline__ unsigned bfpack(float f_even, float f_odd) {
    unsigned r; asm("cvt.rn.bf16x2.f32 %0, %1, %2;" : "=r"(r) : "f"(f_odd), "f"(f_even)); return r;
}
__device__ __forceinline__ float bflo(unsigned u) { return __uint_as_float(u << 16); }
__device__ __forceinline__ float bfhi(unsigned u) { return __uint_as_float(u & 0xffff0000u); }

__device__ __forceinline__ void mma_bf16(float* c, const unsigned* a, unsigned b0, unsigned b1) {
    asm("mma.sync.aligned.m16n8k16.row.col.f32.bf16.bf16.f32 "
        "{%0,%1,%2,%3}, {%4,%5,%6,%7}, {%8,%9}, {%0,%1,%2,%3};"
        : "+f"(c[0]), "+f"(c[1]), "+f"(c[2]), "+f"(c[3])
        : "r"(a[0]), "r"(a[1]), "r"(a[2]), "r"(a[3]), "r"(b0), "r"(b1));
}

// smem word layout (total 51696 words = 206784 B):
//   [0..15600)       halo  [60][260]   (6x10 slots, 256 ch + 4 pad)
//   [15600..19824)   xhi   [32][132]   | overlay after mma: ts[32][68]
//   [19824..24048)   xlo   [32][132]
//   [24048..33264)   w1hi  [128][72]   (ALL K resident; built once per block)
//   [33264..42480)   w1lo  [128][72]
//   [42480..50672)   W2p   ull[16][64][4]  packed col-pairs (once per block)
//   [50672..51696)   w8s   [16][64]        9th column (once per block)
#define OFF_XHI  15600
#define OFF_XLO  19824
#define OFF_W1HI 24048
#define OFF_W1LO 33264
#define OFF_W2P  42480
#define OFF_W8   50672
#define SM_WORDS 51696

__device__ __forceinline__ void prefetch_halo(float* dst, const float* __restrict__ x,
                                              int t, int tid) {
    const int b  = t >> 7;
    const int h0 = ((t >> 3) & 15) * 4;
    const int w0 = (t & 7) * 8;
    for (int i = tid; i < 3840; i += 512) {      // 60 slots x 64 float4
        int slot = i >> 6, c4 = i & 63;
        int py = slot / 10, px = slot - py * 10;
        int gh = h0 + py - 1, gw = w0 + px - 1;
        bool ok = ((unsigned)gh < 64u) && ((unsigned)gw < 64u);
        const float* src = x + ((size_t)((b * 64 + (ok ? gh : 0)) * 64 + (ok ? gw : 0))) * 256 + c4 * 4;
        unsigned saddr = (unsigned)__cvta_generic_to_shared(dst + slot * 260 + c4 * 4);
        int n = ok ? 16 : 0;
        asm volatile("cp.async.cg.shared.global [%0], [%1], 16, %2;"
                     :: "r"(saddr), "l"(src), "r"(n));
    }
}

__global__ void __launch_bounds__(512, 1) invo_fused(
    const float* __restrict__ x,
    const float* __restrict__ W1, const float* __restrict__ b1,
    const float* __restrict__ W2, const float* __restrict__ b2,
    float* __restrict__ out)
{
    extern __shared__ float sm[];
    float*    halo = sm;
    unsigned* xhi  = (unsigned*)(sm + OFF_XHI);   // [32][132]
    unsigned* xlo  = (unsigned*)(sm + OFF_XLO);   // [32][132]
    unsigned* w1hi = (unsigned*)(sm + OFF_W1HI);  // [128][72]
    unsigned* w1lo = (unsigned*)(sm + OFF_W1LO);  // [128][72]
    ull*      W2p  = (ull*)(sm + OFF_W2P);        // [16*64*4]
    float*    w8s  = sm + OFF_W8;                 // [16*64]
    float*    ts   = sm + OFF_XHI;                // overlay [32][68]

    const int tid  = threadIdx.x;
    const int w    = tid >> 5, lane = tid & 31;
    const int quad = lane >> 2, tq = lane & 3;
    const int mw   = w & 1,  nw = w >> 1;         // 2m x 8n warp grid (M=32, N=64)
    const int g    = w;                           // group per warp (stage B + invo)
    const int py0  = lane >> 3, pxx = lane & 7;   // pixel per lane (4x8)

    // ---- prologue: first halo prefetch; W1 hi/lo (ALL K) + W2 packing (once) ----
    prefetch_halo(halo, x, blockIdx.x, tid);
    asm volatile("cp.async.commit_group;");

    for (int i = tid; i < 8192; i += 512) {       // W1: 128 k-pairs x 64 cols
        int kpl = i >> 6, c = i & 63;
        float f0 = W1[(size_t)(2 * kpl) * 64 + c];
        float f1 = W1[(size_t)(2 * kpl + 1) * 64 + c];
        unsigned h = bfpack(f0, f1);
        unsigned l = bfpack(f0 - bflo(h), f1 - bfhi(h));
        w1hi[kpl * 72 + c] = h;
        w1lo[kpl * 72 + c] = l;
    }
    for (int i = tid; i < 4096; i += 512) {       // W2p[g][k][jp] packed col-pairs
        int gg = i >> 8, rem = i & 255;
        int k = rem >> 2, jp = rem & 3;
        W2p[i] = pack2(W2[k * 144 + gg * 9 + 2 * jp], W2[k * 144 + gg * 9 + 2 * jp + 1]);
    }
    for (int i = tid; i < 1024; i += 512) {       // w8s[g][k]
        int gg = i >> 6, k = i & 63;
        w8s[i] = W2[k * 144 + gg * 9 + 8];
    }

    // per-thread constants hoisted out of the tile loop
    const int nb = nw * 8 + 2 * tq;               // ts write cols
    const float bia0 = b1[nb], bia1 = b1[nb + 1];
    ull  binit[4];
    float b8init;
    {
        const float* bb = b2 + g * 9;
        binit[0] = pack2(bb[0], bb[1]); binit[1] = pack2(bb[2], bb[3]);
        binit[2] = pack2(bb[4], bb[5]); binit[3] = pack2(bb[6], bb[7]);
        b8init = bb[8];
    }

    for (int t = blockIdx.x; t < NTILE; t += NBLK) {
        const int b  = t >> 7;
        const int h0 = ((t >> 3) & 15) * 4;
        const int w0 = (t & 7) * 8;

        asm volatile("cp.async.wait_group 0;");
        __syncthreads();          // halo ready; prologue smem ready; prev tile done

        // ---- x -> bf16 hi/lo pairs (full 256 ch) ----
        for (int i = tid; i < 2048; i += 512) {   // 32 px x 64 float4
            int r = i >> 6, c4 = i & 63;
            int slot = ((r >> 3) + 1) * 10 + (r & 7) + 1;
            float4 v = *(const float4*)&halo[slot * 260 + c4 * 4];
            unsigned h0v = bfpack(v.x, v.y);
            unsigned l0v = bfpack(v.x - bflo(h0v), v.y - bfhi(h0v));
            unsigned h1v = bfpack(v.z, v.w);
            unsigned l1v = bfpack(v.z - bflo(h1v), v.w - bfhi(h1v));
            int base = r * 132 + 2 * c4;
            xhi[base] = h0v; xhi[base + 1] = h1v;
            xlo[base] = l0v; xlo[base + 1] = l1v;
        }
        __syncthreads();

        // ---- Stage A: one m16n8 tile per warp, K=256 (16 k16-steps, 3-mma split) ----
        float cfr[4] = {0.f, 0.f, 0.f, 0.f};
        {
            const int r0 = mw * 16 + quad;
            const unsigned* xh0 = &xhi[r0 * 132];
            const unsigned* xh8 = &xhi[(r0 + 8) * 132];
            const unsigned* xl0 = &xlo[r0 * 132];
            const unsigned* xl8 = &xlo[(r0 + 8) * 132];
            const int n0 = nw * 8 + quad;
            #pragma unroll
            for (int ks = 0; ks < 16; ks++) {
                const int kp = 8 * ks + tq;
                unsigned ah[4], al[4];
                ah[0] = xh0[kp];     ah[1] = xh8[kp];
                ah[2] = xh0[kp + 4]; ah[3] = xh8[kp + 4];
                al[0] = xl0[kp];     al[1] = xl8[kp];
                al[2] = xl0[kp + 4]; al[3] = xl8[kp + 4];
                unsigned b0h = w1hi[kp * 72 + n0];
                unsigned b1h = w1hi[(kp + 4) * 72 + n0];
                unsigned b0l = w1lo[kp * 72 + n0];
                unsigned b1l = w1lo[(kp + 4) * 72 + n0];
                mma_bf16(cfr, ah, b0h, b1h);
                mma_bf16(cfr, ah, b0l, b1l);
                mma_bf16(cfr, al, b0h, b1h);
            }
        }
        __syncthreads();          // xhi/xlo dead -> ts overlay safe

        // ---- write ts (+b1) ----
        {
            const int r0 = mw * 16 + quad;
            ts[r0 * 68 + nb]           = cfr[0] + bia0;
            ts[r0 * 68 + nb + 1]       = cfr[1] + bia1;
            ts[(r0 + 8) * 68 + nb]     = cfr[2] + bia0;
            ts[(r0 + 8) * 68 + nb + 1] = cfr[3] + bia1;
        }
        __syncthreads();

        // ---- Stage B: 1 px (lane) x 1 g (warp) per thread; wgt stays in regs ----
        ull  acc[4] = {binit[0], binit[1], binit[2], binit[3]};
        float acc8 = b8init;
        {
            const float* tr = &ts[lane * 68];
            const ull*   wp = &W2p[g * 256];      // [k][jp]
            const float* w8 = &w8s[g * 64];
            for (int k = 0; k < 64; k += 4) {
                float4 t0  = *(const float4*)&tr[k];
                float4 w84 = *(const float4*)&w8[k];          // uniform
                #pragma unroll
                for (int kk = 0; kk < 4; kk++) {
                    ulonglong2 wp0 = *(const ulonglong2*)&wp[(k + kk) * 4];      // uniform
                    ulonglong2 wp1 = *(const ulonglong2*)&wp[(k + kk) * 4 + 2];  // uniform
                    float a = (&t0.x)[kk];
                    ull A = pack2(a, a);
                    ffma2(acc[0], A, wp0.x); ffma2(acc[1], A, wp0.y);
                    ffma2(acc[2], A, wp1.x); ffma2(acc[3], A, wp1.y);
                    acc8 = fmaf(a, (&w84.x)[kk], acc8);
                }
            }
        }
        float wr[9];
        unpack2(acc[0], wr[0], wr[1]); unpack2(acc[1], wr[2], wr[3]);
        unpack2(acc[2], wr[4], wr[5]); unpack2(acc[3], wr[6], wr[7]);
        wr[8] = acc8;

        // ---- involution (reads halo + wr regs); 1 px x 1 g per thread ----
        const int base0 = (py0 * 10 + pxx) * 260;
        float* orow = out + ((size_t)((b * 64 + h0 + py0) * 64 + w0 + pxx)) * 256 + g * 16;

        #pragma unroll
        for (int gcc = 0; gcc < 4; gcc++) {
            float o0[4] = {0.f, 0.f, 0.f, 0.f};
            #pragma unroll
            for (int u = 0; u < 9; u++) {
                int f  = g * 144 + gcc * 36 + 4 * u;
                int n  = f >> 8;              // neighbor, constant across the float4
                int ch = f & 255;
                int ni = n / 3, nj = n - ni * 3;
                float4 v0 = *(const float4*)&halo[base0 + (ni * 10 + nj) * 260 + ch];
                const int i0 = 4 * u;
                o0[(i0 + 0) / 9] = fmaf(wr[(i0 + 0) % 9], v0.x, o0[(i0 + 0) / 9]);
                o0[(i0 + 1) / 9] = fmaf(wr[(i0 + 1) % 9], v0.y, o0[(i0 + 1) / 9]);
                o0[(i0 + 2) / 9] = fmaf(wr[(i0 + 2) % 9], v0.z, o0[(i0 + 2) / 9]);
                o0[(i0 + 3) / 9] = fmaf(wr[(i0 + 3) % 9], v0.w, o0[(i0 + 3) / 9]);
            }
            *(float4*)&orow[gcc * 4] = make_float4(o0[0], o0[1], o0[2], o0[3]);
        }
        __syncthreads();          // halo consumed; safe to prefetch next tile

        if (t + NBLK < NTILE) {
            prefetch_halo(halo, x, t + NBLK, tid);
            asm volatile("cp.async.commit_group;");
        }
    }
}

extern "C" void kernel_launch(void* const* d_in, const int* in_sizes, int n_in,
                              void* d_out, int out_size) {
    const float* x  = (const float*)d_in[0];
    const float* W1 = (const float*)d_in[1];
    const float* b1 = (const float*)d_in[2];
    const float* W2 = (const float*)d_in[3];
    const float* b2 = (const float*)d_in[4];
    float* out = (float*)d_out;

    const int SM = SM_WORDS * 4;   // 206784 B
    cudaFuncSetAttribute(invo_fused, cudaFuncAttributeMaxDynamicSharedMemorySize, SM);
    invo_fused<<<NBLK, 512, SM>>>(x, W1, b1, W2, b2, out);
}